// round 1
// baseline (speedup 1.0000x reference)
#include <cuda_runtime.h>
#include <math.h>

// Problem constants (KWinners2d: B=64, C=128, H=W=56)
#define NB      64
#define NC      128
#define HW      3136
#define NPB     401408          // per-batch n = C*H*W
#define NPB4    (NPB/4)         // 100352 float4 per batch
#define HW4     (HW/4)          // 784
#define NBINS   8192            // 13-bit coarse histogram
#define CAP     (1<<17)         // candidate buffer per batch
#define CPB_A   8               // CTAs per batch, histogram pass
#define CPB_C   16              // CTAs per batch, write pass

// -------- global scratch (static __device__, no allocation) --------
__device__ unsigned int       g_hist[NB * NBINS];
__device__ unsigned int       g_cand_cnt[NB];
__device__ unsigned int       g_bstar[NB];
__device__ unsigned int       g_above[NB];
__device__ unsigned long long g_cand[(size_t)NB * CAP];  // (key<<32)|idx

// order-preserving key for f32: larger float -> larger uint
__device__ __forceinline__ unsigned okey(float f) {
    unsigned u = __float_as_uint(f);
    return (u & 0x80000000u) ? ~u : (u | 0x80000000u);
}

__device__ __forceinline__ float boost_factor(int k, float duty) {
    // reference: f32(k/n) - duty (f32 sub), then exp (f32).
    // use double exp of the f32 argument, rounded to f32 (correctly rounded).
    float td = (float)((double)k / (double)NPB);
    float arg = td - duty;
    return (float)exp((double)arg);
}

// -------- kernel 0: zero scratch (must re-zero every graph replay) --------
__global__ void zero_kernel() {
    int total = NB * NBINS;
    for (int i = blockIdx.x * blockDim.x + threadIdx.x; i < total;
         i += gridDim.x * blockDim.x)
        g_hist[i] = 0;
    if (blockIdx.x == 0 && threadIdx.x < NB) g_cand_cnt[threadIdx.x] = 0;
}

// -------- kernel 1: per-batch coarse histogram (13 key bits) --------
__global__ void hist_kernel(const float* __restrict__ x,
                            const float* __restrict__ duty,
                            const int* __restrict__ kp) {
    __shared__ unsigned s_hist[NBINS];
    __shared__ float    s_fac[NC];
    int tid = threadIdx.x;
    for (int i = tid; i < NBINS; i += blockDim.x) s_hist[i] = 0;
    if (tid < NC) s_fac[tid] = boost_factor(*kp, duty[tid]);
    __syncthreads();

    int batch = blockIdx.x / CPB_A;
    int slice = blockIdx.x % CPB_A;
    const float4* x4 = (const float4*)x + (size_t)batch * NPB4;
    const int PER = NPB4 / CPB_A;              // 12544
    int base = slice * PER;
    for (int i = tid; i < PER; i += blockDim.x) {
        int q = base + i;
        float f = s_fac[q / HW4];
        float4 v = x4[q];
        atomicAdd(&s_hist[okey(v.x * f) >> 19], 1u);
        atomicAdd(&s_hist[okey(v.y * f) >> 19], 1u);
        atomicAdd(&s_hist[okey(v.z * f) >> 19], 1u);
        atomicAdd(&s_hist[okey(v.w * f) >> 19], 1u);
    }
    __syncthreads();
    unsigned* gh = &g_hist[batch * NBINS];
    for (int i = tid; i < NBINS; i += blockDim.x)
        if (s_hist[i]) atomicAdd(&gh[i], s_hist[i]);
}

// -------- kernel 2: per batch, find bin containing the k-th largest --------
__global__ void findbin_kernel(const int* __restrict__ kp) {
    __shared__ unsigned s_sum[256];
    int batch = blockIdx.x, tid = threadIdx.x;
    const unsigned* gh = &g_hist[batch * NBINS];
    // thread t sums a descending chunk of 32 bins
    unsigned s = 0;
    int hi = NBINS - 1 - tid * 32;
    for (int j = 0; j < 32; j++) s += gh[hi - j];
    s_sum[tid] = s;
    __syncthreads();
    if (tid == 0) {
        unsigned k = (unsigned)(*kp);
        unsigned cum = 0;
        for (int j = 0; j < 256; j++) {
            if (cum + s_sum[j] >= k) {
                for (int b = NBINS - 1 - j * 32;; b--) {
                    unsigned h = gh[b];
                    if (cum + h >= k) { g_bstar[batch] = (unsigned)b; g_above[batch] = cum; break; }
                    cum += h;
                }
                break;
            }
            cum += s_sum[j];
        }
    }
}

// warp-aggregated candidate push
__device__ __forceinline__ void push_cand(int batch, unsigned key, unsigned idx,
                                          bool active, int lane) {
    unsigned mask = __ballot_sync(0xffffffffu, active);
    if (mask) {
        int leader = __ffs(mask) - 1;
        unsigned base = 0;
        if (lane == leader) base = atomicAdd(&g_cand_cnt[batch], (unsigned)__popc(mask));
        base = __shfl_sync(0xffffffffu, base, leader);
        if (active) {
            unsigned pos = base + __popc(mask & ((1u << lane) - 1u));
            if (pos < CAP)
                g_cand[(size_t)batch * CAP + pos] =
                    ((unsigned long long)key << 32) | (unsigned long long)idx;
        }
    }
}

// -------- kernel 3: write clear winners/losers, compact boundary bin --------
__global__ void write_kernel(const float* __restrict__ x,
                             const float* __restrict__ duty,
                             const int* __restrict__ kp,
                             float* __restrict__ out) {
    __shared__ float s_fac[NC];
    int tid = threadIdx.x;
    if (tid < NC) s_fac[tid] = boost_factor(*kp, duty[tid]);
    __syncthreads();

    int batch = blockIdx.x / CPB_C;
    int slice = blockIdx.x % CPB_C;
    unsigned bstar = g_bstar[batch];
    const float4* x4 = (const float4*)x + (size_t)batch * NPB4;
    float4*       o4 = (float4*)out     + (size_t)batch * NPB4;
    int lane = tid & 31;
    const int PER = NPB4 / CPB_C;              // 6272
    // loop trip count is identical across a warp (contiguous tids) -> ballots safe
    for (int i = tid; i < PER; i += blockDim.x) {
        int q = slice * PER + i;
        float f = s_fac[q / HW4];
        float4 v = x4[q];
        unsigned k0 = okey(v.x * f), k1 = okey(v.y * f);
        unsigned k2 = okey(v.z * f), k3 = okey(v.w * f);
        float4 o;
        o.x = ((k0 >> 19) > bstar) ? v.x : 0.0f;
        o.y = ((k1 >> 19) > bstar) ? v.y : 0.0f;
        o.z = ((k2 >> 19) > bstar) ? v.z : 0.0f;
        o.w = ((k3 >> 19) > bstar) ? v.w : 0.0f;
        o4[q] = o;
        unsigned e = (unsigned)q * 4u;
        push_cand(batch, k0, e + 0u, (k0 >> 19) == bstar, lane);
        push_cand(batch, k1, e + 1u, (k1 >> 19) == bstar, lane);
        push_cand(batch, k2, e + 2u, (k2 >> 19) == bstar, lane);
        push_cand(batch, k3, e + 3u, (k3 >> 19) == bstar, lane);
    }
}

// -------- kernel 4: exact selection among boundary-bin candidates --------
__global__ void final_kernel(const float* __restrict__ x,
                             const int* __restrict__ kp,
                             float* __restrict__ out) {
    __shared__ unsigned s_h[2048];
    __shared__ unsigned s_chunk[64];
    __shared__ unsigned s_eq[2048];
    __shared__ unsigned s_eqcnt, s_b1, s_g1, s_tl, s_r2;
    int batch = blockIdx.x, tid = threadIdx.x, nt = blockDim.x;
    unsigned m = min(g_cand_cnt[batch], (unsigned)CAP);
    unsigned k = (unsigned)(*kp);
    unsigned r = k - g_above[batch];           // winners still needed, 1..m
    const unsigned long long* cand = &g_cand[(size_t)batch * CAP];
    const float* xb = x   + (size_t)batch * NPB;
    float*       ob = out + (size_t)batch * NPB;

    if (r >= m) {                               // everything in the bin wins
        for (unsigned j = tid; j < m; j += nt) {
            unsigned idx = (unsigned)cand[j];
            ob[idx] = xb[idx];
        }
        return;
    }

    // level 1: histogram on key bits [18:8]
    for (int i = tid; i < 2048; i += nt) s_h[i] = 0;
    __syncthreads();
    for (unsigned j = tid; j < m; j += nt) {
        unsigned key = (unsigned)(cand[j] >> 32);
        atomicAdd(&s_h[(key >> 8) & 0x7FFu], 1u);
    }
    __syncthreads();
    if (tid < 64) {
        unsigned s = 0; int hi = 2047 - tid * 32;
        for (int j = 0; j < 32; j++) s += s_h[hi - j];
        s_chunk[tid] = s;
    }
    __syncthreads();
    if (tid == 0) {
        unsigned cum = 0;
        for (int j = 0; j < 64; j++) {
            if (cum + s_chunk[j] >= r) {
                for (int b = 2047 - 32 * j;; b--) {
                    unsigned h = s_h[b];
                    if (cum + h >= r) { s_b1 = (unsigned)b; s_g1 = cum; break; }
                    cum += h;
                }
                break;
            }
            cum += s_chunk[j];
        }
    }
    __syncthreads();
    unsigned b1 = s_b1, g1 = s_g1;

    // level 2: histogram on key bits [7:0] among b1 matches
    for (int i = tid; i < 256; i += nt) s_h[i] = 0;
    __syncthreads();
    for (unsigned j = tid; j < m; j += nt) {
        unsigned key = (unsigned)(cand[j] >> 32);
        if (((key >> 8) & 0x7FFu) == b1) atomicAdd(&s_h[key & 0xFFu], 1u);
    }
    __syncthreads();
    if (tid == 0) {
        unsigned cum = g1;
        for (int b = 255;; b--) {
            unsigned h = s_h[b];
            if (cum + h >= r) { s_tl = (b1 << 8) | (unsigned)b; s_r2 = r - cum; break; }
            cum += h;
        }
        s_eqcnt = 0;
    }
    __syncthreads();
    unsigned tl = s_tl, r2 = s_r2;

    // write strict winners; collect exact-threshold ties
    for (unsigned j = tid; j < m; j += nt) {
        unsigned long long cv = cand[j];
        unsigned key = (unsigned)(cv >> 32);
        unsigned l = key & 0x7FFFFu;
        unsigned idx = (unsigned)cv;
        if (l > tl) ob[idx] = xb[idx];
        else if (l == tl) {
            unsigned p = atomicAdd(&s_eqcnt, 1u);
            if (p < 2048u) s_eq[p] = idx;
        }
    }
    __syncthreads();
    unsigned e = min(s_eqcnt, 2048u);
    if (r2 >= e) {
        for (unsigned j = tid; j < e; j += nt) { unsigned idx = s_eq[j]; ob[idx] = xb[idx]; }
    } else {
        // ties broken by LOWEST index (matches jax.lax.top_k)
        for (unsigned j = tid; j < e; j += nt) {
            unsigned idx = s_eq[j], rank = 0;
            for (unsigned l2 = 0; l2 < e; l2++) rank += (s_eq[l2] < idx) ? 1u : 0u;
            if (rank < r2) ob[idx] = xb[idx];
        }
    }
}

extern "C" void kernel_launch(void* const* d_in, const int* in_sizes, int n_in,
                              void* d_out, int out_size) {
    const float* x    = (const float*)d_in[0];
    const float* duty = (const float*)d_in[1];
    const int*   kp   = (const int*)d_in[2];
    float*       out  = (float*)d_out;

    zero_kernel<<<256, 256>>>();
    hist_kernel<<<NB * CPB_A, 256>>>(x, duty, kp);
    findbin_kernel<<<NB, 256>>>(kp);
    write_kernel<<<NB * CPB_C, 256>>>(x, duty, kp, out);
    final_kernel<<<NB, 256>>>(x, kp, out);
}

// round 2
// speedup vs baseline: 1.6843x; 1.6843x over previous
#include <cuda_runtime.h>
#include <math.h>

// Problem constants (KWinners2d: B=64, C=128, H=W=56)
#define NB      64
#define NC      128
#define HW      3136
#define NPB     401408          // per-batch n = C*H*W
#define NPB4    (NPB/4)         // 100352 float4 per batch
#define HW4     (HW/4)          // 784
#define NBINS   8192            // 13-bit coarse histogram
#define CAP     (1<<17)         // candidate buffer per batch
#define CPB_A   8               // CTAs per batch, histogram pass
#define CPB_C   16              // CTAs per batch, write pass
#define STAGE   2048            // per-CTA candidate staging entries

// -------- global scratch (static __device__, no allocation) --------
__device__ unsigned int       g_hist[NB * NBINS];
__device__ unsigned int       g_cand_cnt[NB];
__device__ unsigned int       g_bstar[NB];
__device__ unsigned int       g_above[NB];
__device__ unsigned long long g_cand[(size_t)NB * CAP];  // (key<<32)|idx

// order-preserving key for f32: larger float -> larger uint
__device__ __forceinline__ unsigned okey(float f) {
    unsigned u = __float_as_uint(f);
    return (u & 0x80000000u) ? ~u : (u | 0x80000000u);
}

__device__ __forceinline__ float boost_factor(int k, float duty) {
    // reference: f32(k/n) - duty (f32 sub), then f32 exp.
    // double-precision exp of the f32 argument, rounded to f32 (correctly rounded).
    float td = (float)((double)k / (double)NPB);
    float arg = td - duty;
    return (float)exp((double)arg);
}

// -------- kernel 0: zero scratch (re-zeroed every graph replay) --------
__global__ void zero_kernel() {
    int total = NB * NBINS;
    for (int i = blockIdx.x * blockDim.x + threadIdx.x; i < total;
         i += gridDim.x * blockDim.x)
        g_hist[i] = 0;
    if (blockIdx.x == 0 && threadIdx.x < NB) g_cand_cnt[threadIdx.x] = 0;
}

// -------- kernel 1: per-batch coarse histogram (13 key bits) --------
__global__ void hist_kernel(const float* __restrict__ x,
                            const float* __restrict__ duty,
                            const int* __restrict__ kp) {
    __shared__ unsigned s_hist[NBINS];
    __shared__ float    s_fac[NC];
    int tid = threadIdx.x;
    for (int i = tid; i < NBINS; i += 256) s_hist[i] = 0;
    if (tid < NC) s_fac[tid] = boost_factor(*kp, duty[tid]);
    __syncthreads();

    int batch = blockIdx.x / CPB_A;
    int slice = blockIdx.x % CPB_A;
    const float4* x4 = (const float4*)x + (size_t)batch * NPB4;
    const int PER = NPB4 / CPB_A;              // 12544
    int base = slice * PER;
    for (int i = tid; i < PER; i += 256) {
        int q = base + i;
        float f = s_fac[q / HW4];
        float4 v = x4[q];
        unsigned b0 = okey(v.x * f) >> 19;
        unsigned b1 = okey(v.y * f) >> 19;
        unsigned b2 = okey(v.z * f) >> 19;
        unsigned b3 = okey(v.w * f) >> 19;
        // merge duplicate bins among the 4 to cut shared-atomic serialization
        unsigned c0 = 1, c1 = 1, c2 = 1, c3 = 1;
        if (b1 == b0) { c0++; c1 = 0; }
        if (b2 == b0) { c0++; c2 = 0; }
        else if (c1 && b2 == b1) { c1++; c2 = 0; }
        if (b3 == b0) { c0++; c3 = 0; }
        else if (c1 && b3 == b1) { c1++; c3 = 0; }
        else if (c2 && b3 == b2) { c2++; c3 = 0; }
        atomicAdd(&s_hist[b0], c0);
        if (c1) atomicAdd(&s_hist[b1], c1);
        if (c2) atomicAdd(&s_hist[b2], c2);
        if (c3) atomicAdd(&s_hist[b3], c3);
    }
    __syncthreads();
    unsigned* gh = &g_hist[batch * NBINS];
    for (int i = tid; i < NBINS; i += 256)
        if (s_hist[i]) atomicAdd(&gh[i], s_hist[i]);
}

// -------- kernel 2: per batch, find bin containing the k-th largest --------
__global__ void findbin_kernel(const int* __restrict__ kp) {
    __shared__ unsigned s_sum[256];
    int batch = blockIdx.x, tid = threadIdx.x;
    const unsigned* gh = &g_hist[batch * NBINS];
    unsigned s = 0;
    int hi = NBINS - 1 - tid * 32;
    for (int j = 0; j < 32; j++) s += gh[hi - j];
    s_sum[tid] = s;
    __syncthreads();
    if (tid == 0) {
        unsigned k = (unsigned)(*kp);
        unsigned cum = 0;
        for (int j = 0; j < 256; j++) {
            if (cum + s_sum[j] >= k) {
                for (int b = NBINS - 1 - j * 32;; b--) {
                    unsigned h = gh[b];
                    if (cum + h >= k) { g_bstar[batch] = (unsigned)b; g_above[batch] = cum; break; }
                    cum += h;
                }
                break;
            }
            cum += s_sum[j];
        }
    }
}

// -------- kernel 3: write clear winners/losers, stage boundary bin in smem --------
__global__ void __launch_bounds__(256) write_kernel(
        const float* __restrict__ x,
        const float* __restrict__ duty,
        const int* __restrict__ kp,
        float* __restrict__ out) {
    __shared__ float             s_fac[NC];
    __shared__ unsigned long long s_buf[STAGE];
    __shared__ unsigned          s_cnt;
    int tid = threadIdx.x;
    if (tid < NC) s_fac[tid] = boost_factor(*kp, duty[tid]);
    if (tid == 0) s_cnt = 0;
    __syncthreads();

    int batch = blockIdx.x / CPB_C;
    int slice = blockIdx.x % CPB_C;
    unsigned bstar = g_bstar[batch];
    const float4* x4 = (const float4*)x + (size_t)batch * NPB4;
    float4*       o4 = (float4*)out     + (size_t)batch * NPB4;
    const int PER = NPB4 / CPB_C;              // 6272

    #pragma unroll 2
    for (int i = tid; i < PER; i += 256) {
        int q = slice * PER + i;
        float f = s_fac[q / HW4];
        float4 v = x4[q];
        unsigned k0 = okey(v.x * f), k1 = okey(v.y * f);
        unsigned k2 = okey(v.z * f), k3 = okey(v.w * f);
        unsigned b0 = k0 >> 19, b1 = k1 >> 19, b2 = k2 >> 19, b3 = k3 >> 19;
        float4 o;
        o.x = (b0 > bstar) ? v.x : 0.0f;
        o.y = (b1 > bstar) ? v.y : 0.0f;
        o.z = (b2 > bstar) ? v.z : 0.0f;
        o.w = (b3 > bstar) ? v.w : 0.0f;
        o4[q] = o;
        unsigned e = (unsigned)q * 4u;
        // rare path: ~1% of elements land in the boundary bin
        if (b0 == bstar) {
            unsigned p = atomicAdd(&s_cnt, 1u);
            unsigned long long cv = ((unsigned long long)k0 << 32) | (e + 0u);
            if (p < STAGE) s_buf[p] = cv;
            else { unsigned g = atomicAdd(&g_cand_cnt[batch], 1u);
                   if (g < CAP) g_cand[(size_t)batch * CAP + g] = cv; }
        }
        if (b1 == bstar) {
            unsigned p = atomicAdd(&s_cnt, 1u);
            unsigned long long cv = ((unsigned long long)k1 << 32) | (e + 1u);
            if (p < STAGE) s_buf[p] = cv;
            else { unsigned g = atomicAdd(&g_cand_cnt[batch], 1u);
                   if (g < CAP) g_cand[(size_t)batch * CAP + g] = cv; }
        }
        if (b2 == bstar) {
            unsigned p = atomicAdd(&s_cnt, 1u);
            unsigned long long cv = ((unsigned long long)k2 << 32) | (e + 2u);
            if (p < STAGE) s_buf[p] = cv;
            else { unsigned g = atomicAdd(&g_cand_cnt[batch], 1u);
                   if (g < CAP) g_cand[(size_t)batch * CAP + g] = cv; }
        }
        if (b3 == bstar) {
            unsigned p = atomicAdd(&s_cnt, 1u);
            unsigned long long cv = ((unsigned long long)k3 << 32) | (e + 3u);
            if (p < STAGE) s_buf[p] = cv;
            else { unsigned g = atomicAdd(&g_cand_cnt[batch], 1u);
                   if (g < CAP) g_cand[(size_t)batch * CAP + g] = cv; }
        }
    }
    __syncthreads();

    // flush staged candidates: one global atomic per CTA, coalesced copy
    __shared__ unsigned s_base;
    unsigned cnt = min(s_cnt, (unsigned)STAGE);
    if (tid == 0) s_base = atomicAdd(&g_cand_cnt[batch], cnt);
    __syncthreads();
    unsigned base = s_base;
    for (unsigned j = tid; j < cnt; j += 256) {
        unsigned pos = base + j;
        if (pos < CAP) g_cand[(size_t)batch * CAP + pos] = s_buf[j];
    }
}

// -------- kernel 4: exact selection among boundary-bin candidates --------
__global__ void final_kernel(const float* __restrict__ x,
                             const int* __restrict__ kp,
                             float* __restrict__ out) {
    __shared__ unsigned s_h[2048];
    __shared__ unsigned s_chunk[64];
    __shared__ unsigned s_eq[2048];
    __shared__ unsigned s_eqcnt, s_b1, s_g1, s_tl, s_r2;
    int batch = blockIdx.x, tid = threadIdx.x, nt = blockDim.x;
    unsigned m = min(g_cand_cnt[batch], (unsigned)CAP);
    unsigned k = (unsigned)(*kp);
    unsigned r = k - g_above[batch];           // winners still needed, 1..m
    const unsigned long long* cand = &g_cand[(size_t)batch * CAP];
    const float* xb = x   + (size_t)batch * NPB;
    float*       ob = out + (size_t)batch * NPB;

    if (r >= m) {                               // everything in the bin wins
        for (unsigned j = tid; j < m; j += nt) {
            unsigned idx = (unsigned)cand[j];
            ob[idx] = xb[idx];
        }
        return;
    }

    // level 1: histogram on key bits [18:8]
    for (int i = tid; i < 2048; i += nt) s_h[i] = 0;
    __syncthreads();
    for (unsigned j = tid; j < m; j += nt) {
        unsigned key = (unsigned)(cand[j] >> 32);
        atomicAdd(&s_h[(key >> 8) & 0x7FFu], 1u);
    }
    __syncthreads();
    if (tid < 64) {
        unsigned s = 0; int hi = 2047 - tid * 32;
        for (int j = 0; j < 32; j++) s += s_h[hi - j];
        s_chunk[tid] = s;
    }
    __syncthreads();
    if (tid == 0) {
        unsigned cum = 0;
        for (int j = 0; j < 64; j++) {
            if (cum + s_chunk[j] >= r) {
                for (int b = 2047 - 32 * j;; b--) {
                    unsigned h = s_h[b];
                    if (cum + h >= r) { s_b1 = (unsigned)b; s_g1 = cum; break; }
                    cum += h;
                }
                break;
            }
            cum += s_chunk[j];
        }
    }
    __syncthreads();
    unsigned b1 = s_b1, g1 = s_g1;

    // level 2: histogram on key bits [7:0] among b1 matches
    for (int i = tid; i < 256; i += nt) s_h[i] = 0;
    __syncthreads();
    for (unsigned j = tid; j < m; j += nt) {
        unsigned key = (unsigned)(cand[j] >> 32);
        if (((key >> 8) & 0x7FFu) == b1) atomicAdd(&s_h[key & 0xFFu], 1u);
    }
    __syncthreads();
    if (tid == 0) {
        unsigned cum = g1;
        for (int b = 255;; b--) {
            unsigned h = s_h[b];
            if (cum + h >= r) { s_tl = (b1 << 8) | (unsigned)b; s_r2 = r - cum; break; }
            cum += h;
        }
        s_eqcnt = 0;
    }
    __syncthreads();
    unsigned tl = s_tl, r2 = s_r2;

    // write strict winners; collect exact-threshold ties
    for (unsigned j = tid; j < m; j += nt) {
        unsigned long long cv = cand[j];
        unsigned key = (unsigned)(cv >> 32);
        unsigned l = key & 0x7FFFFu;
        unsigned idx = (unsigned)cv;
        if (l > tl) ob[idx] = xb[idx];
        else if (l == tl) {
            unsigned p = atomicAdd(&s_eqcnt, 1u);
            if (p < 2048u) s_eq[p] = idx;
        }
    }
    __syncthreads();
    unsigned e = min(s_eqcnt, 2048u);
    if (r2 >= e) {
        for (unsigned j = tid; j < e; j += nt) { unsigned idx = s_eq[j]; ob[idx] = xb[idx]; }
    } else {
        // ties broken by LOWEST index (matches jax.lax.top_k)
        for (unsigned j = tid; j < e; j += nt) {
            unsigned idx = s_eq[j], rank = 0;
            for (unsigned l2 = 0; l2 < e; l2++) rank += (s_eq[l2] < idx) ? 1u : 0u;
            if (rank < r2) ob[idx] = xb[idx];
        }
    }
}

extern "C" void kernel_launch(void* const* d_in, const int* in_sizes, int n_in,
                              void* d_out, int out_size) {
    const float* x    = (const float*)d_in[0];
    const float* duty = (const float*)d_in[1];
    const int*   kp   = (const int*)d_in[2];
    float*       out  = (float*)d_out;

    zero_kernel<<<256, 256>>>();
    hist_kernel<<<NB * CPB_A, 256>>>(x, duty, kp);
    findbin_kernel<<<NB, 256>>>(kp);
    write_kernel<<<NB * CPB_C, 256>>>(x, duty, kp, out);
    final_kernel<<<NB, 256>>>(x, kp, out);
}